// round 1
// baseline (speedup 1.0000x reference)
#include <cuda_runtime.h>

#define NN 50000
#define NG 500
#define EA 800000
#define EB 3200000
#define HID 128
#define OUTD 64
#define FULLM 0xffffffffu

// ---------------- device scratch (static, no allocation) ----------------
__device__ float g_h[NN * OUTD];
__device__ float g_ssrc[NN];
__device__ float g_sdst[NN];
__device__ float g_x0[NN * HID];
__device__ float g_x1[NN * HID];
__device__ int   g_rowA[NN + 1];
__device__ int   g_colA[EA];
__device__ int   g_curA[NN];
__device__ int   g_rowB[NN + 1];
__device__ int   g_colB[EB];
__device__ int   g_curB[NN];
__device__ float g_pool[NG * HID];

// ---------------- small utility kernels ----------------
__global__ void zero_int_k(int* p, int n) {
    int i = blockIdx.x * blockDim.x + threadIdx.x;
    if (i < n) p[i] = 0;
}
__global__ void zero_float_k(float* p, int n) {
    int i = blockIdx.x * blockDim.x + threadIdx.x;
    if (i < n) p[i] = 0.f;
}
__global__ void copy_int_k(const int* __restrict__ a, int* __restrict__ b, int n) {
    int i = blockIdx.x * blockDim.x + threadIdx.x;
    if (i < n) b[i] = a[i];
}
__global__ void count_k(const int* __restrict__ dst, int E, int* deg) {
    int i = blockIdx.x * blockDim.x + threadIdx.x;
    if (i < E) atomicAdd(&deg[dst[i]], 1);
}
// exclusive scan over n<=50176 elements, one block of 1024 threads
__global__ void scan_k(const int* __restrict__ deg, int* __restrict__ row, int n) {
    __shared__ int part[1024];
    int t = threadIdx.x;
    int C = (n + 1023) / 1024;
    int b = t * C;
    int e = b + C; if (e > n) e = n;
    int s = 0;
    for (int i = b; i < e; ++i) s += deg[i];
    part[t] = s;
    __syncthreads();
    for (int off = 1; off < 1024; off <<= 1) {
        int v = (t >= off) ? part[t - off] : 0;
        __syncthreads();
        part[t] += v;
        __syncthreads();
    }
    int run = (t > 0) ? part[t - 1] : 0;
    for (int i = b; i < e; ++i) { row[i] = run; run += deg[i]; }
    if (t == 1023) row[n] = part[1023];
}
__global__ void fill_k(const int* __restrict__ src, const int* __restrict__ dst, int E,
                       int* cur, int* __restrict__ col) {
    int i = blockIdx.x * blockDim.x + threadIdx.x;
    if (i < E) {
        int p = atomicAdd(&cur[dst[i]], 1);
        col[p] = src[i];
    }
}

// ---------------- per-layer feature transform: h = x@W, s_src, s_dst -----
__global__ void feat_k(const float* __restrict__ x, const float* __restrict__ W,
                       const float* __restrict__ as_, const float* __restrict__ ad_) {
    __shared__ float Ws[HID * OUTD];
    for (int i = threadIdx.x; i < HID * OUTD; i += blockDim.x) Ws[i] = W[i];
    __syncthreads();
    int lane = threadIdx.x & 31;
    int wid = (blockIdx.x * blockDim.x + threadIdx.x) >> 5;
    int nw = (gridDim.x * blockDim.x) >> 5;
    float asl = as_[lane], ash = as_[lane + 32];
    float adl = ad_[lane], adh = ad_[lane + 32];
    for (int n = wid; n < NN; n += nw) {
        const float* xr = x + n * HID;
        float x0 = xr[lane], x1 = xr[lane + 32], x2 = xr[lane + 64], x3 = xr[lane + 96];
        float h0 = 0.f, h1 = 0.f;
#pragma unroll
        for (int k = 0; k < 32; ++k) {
            float xv = __shfl_sync(FULLM, x0, k);
            h0 += xv * Ws[k * OUTD + lane];
            h1 += xv * Ws[k * OUTD + lane + 32];
        }
#pragma unroll
        for (int k = 0; k < 32; ++k) {
            float xv = __shfl_sync(FULLM, x1, k);
            h0 += xv * Ws[(k + 32) * OUTD + lane];
            h1 += xv * Ws[(k + 32) * OUTD + lane + 32];
        }
#pragma unroll
        for (int k = 0; k < 32; ++k) {
            float xv = __shfl_sync(FULLM, x2, k);
            h0 += xv * Ws[(k + 64) * OUTD + lane];
            h1 += xv * Ws[(k + 64) * OUTD + lane + 32];
        }
#pragma unroll
        for (int k = 0; k < 32; ++k) {
            float xv = __shfl_sync(FULLM, x3, k);
            h0 += xv * Ws[(k + 96) * OUTD + lane];
            h1 += xv * Ws[(k + 96) * OUTD + lane + 32];
        }
        g_h[n * OUTD + lane] = h0;
        g_h[n * OUTD + lane + 32] = h1;
        float s = h0 * asl + h1 * ash;
        float d = h0 * adl + h1 * adh;
#pragma unroll
        for (int o = 16; o; o >>= 1) {
            s += __shfl_xor_sync(FULLM, s, o);
            d += __shfl_xor_sync(FULLM, d, o);
        }
        if (lane == 0) { g_ssrc[n] = s; g_sdst[n] = d; }
    }
}

__device__ __forceinline__ float lrelu(float v) { return v > 0.f ? v : 0.2f * v; }

// ------------- GAT aggregation, warp per destination node ---------------
__global__ void agg_k(const int* __restrict__ row, const int* __restrict__ col,
                      const float* __restrict__ bias, float* __restrict__ xout,
                      int outOff) {
    int n = (blockIdx.x * blockDim.x + threadIdx.x) >> 5;
    int lane = threadIdx.x & 31;
    if (n >= NN) return;

    float sd = g_sdst[n];
    int b = row[n], e = row[n + 1];

    float selfsc = lrelu(g_ssrc[n] + sd);
    float m = selfsc;
    for (int j = b + lane; j < e; j += 32)
        m = fmaxf(m, lrelu(g_ssrc[col[j]] + sd));
#pragma unroll
    for (int o = 16; o; o >>= 1) m = fmaxf(m, __shfl_xor_sync(FULLM, m, o));

    float z, a0, a1;
    {   // self loop
        float p = __expf(selfsc - m);
        z = (lane == 0) ? p : 0.f;
        a0 = p * g_h[n * OUTD + lane];
        a1 = p * g_h[n * OUTD + lane + 32];
    }
    for (int j0 = b; j0 < e; j0 += 32) {
        int j = j0 + lane;
        float p = 0.f; int s = 0;
        if (j < e) {
            s = col[j];
            p = __expf(lrelu(g_ssrc[s] + sd) - m);
        }
        z += p;
        int cnt = e - j0; if (cnt > 32) cnt = 32;
        for (int t = 0; t < cnt; ++t) {
            float pe = __shfl_sync(FULLM, p, t);
            int se = __shfl_sync(FULLM, s, t);
            a0 += pe * g_h[se * OUTD + lane];
            a1 += pe * g_h[se * OUTD + lane + 32];
        }
    }
#pragma unroll
    for (int o = 16; o; o >>= 1) z += __shfl_xor_sync(FULLM, z, o);
    float inv = 1.f / z;
    xout[n * HID + outOff + lane]      = fmaxf(a0 * inv + bias[lane], 0.f);
    xout[n * HID + outOff + lane + 32] = fmaxf(a1 * inv + bias[lane + 32], 0.f);
}

// ------------- global add pool + final linear ----------------
__global__ void pool_k(const int* __restrict__ batch, const float* __restrict__ x) {
    int i = blockIdx.x * blockDim.x + threadIdx.x;
    if (i >= NN * HID) return;
    int n = i >> 7, c = i & 127;
    atomicAdd(&g_pool[batch[n] * HID + c], x[i]);
}
__global__ void final_k(const float* __restrict__ fw, const float* __restrict__ fb,
                        float* __restrict__ out) {
    int g = (blockIdx.x * blockDim.x + threadIdx.x) >> 5;
    int lane = threadIdx.x & 31;
    if (g >= NG) return;
    float acc = 0.f;
    for (int k = lane; k < HID; k += 32) acc += g_pool[g * HID + k] * fw[k];
#pragma unroll
    for (int o = 16; o; o >>= 1) acc += __shfl_xor_sync(FULLM, acc, o);
    if (lane == 0) out[g] = acc + fb[0];
}

// ---------------- host launcher ----------------
extern "C" void kernel_launch(void* const* d_in, const int* in_sizes, int n_in,
                              void* d_out, int out_size) {
    const float* x       = (const float*)d_in[0];
    const int*   ei      = (const int*)d_in[1];
    const int*   di      = (const int*)d_in[2];
    const int*   batch   = (const int*)d_in[3];
    const float* lin_w   = (const float*)d_in[4];
    const float* att_src = (const float*)d_in[5];
    const float* att_dst = (const float*)d_in[6];
    const float* bias    = (const float*)d_in[7];
    const float* fw      = (const float*)d_in[8];
    const float* fb      = (const float*)d_in[9];
    float* out = (float*)d_out;

    void* p;
    cudaGetSymbolAddress(&p, g_rowA); int* rowA = (int*)p;
    cudaGetSymbolAddress(&p, g_colA); int* colA = (int*)p;
    cudaGetSymbolAddress(&p, g_curA); int* curA = (int*)p;
    cudaGetSymbolAddress(&p, g_rowB); int* rowB = (int*)p;
    cudaGetSymbolAddress(&p, g_colB); int* colB = (int*)p;
    cudaGetSymbolAddress(&p, g_curB); int* curB = (int*)p;
    cudaGetSymbolAddress(&p, g_x0);   float* x0 = (float*)p;
    cudaGetSymbolAddress(&p, g_x1);   float* x1 = (float*)p;
    cudaGetSymbolAddress(&p, g_pool); float* pool = (float*)p;

    const int* srcA = ei;        const int* dstA = ei + EA;
    const int* srcB = di;        const int* dstB = di + EB;

    // ---- build CSR (by dst) for both edge sets ----
    zero_int_k<<<(NN + 255) / 256, 256>>>(curA, NN);
    zero_int_k<<<(NN + 255) / 256, 256>>>(curB, NN);
    count_k<<<(EA + 255) / 256, 256>>>(dstA, EA, curA);
    count_k<<<(EB + 255) / 256, 256>>>(dstB, EB, curB);
    scan_k<<<1, 1024>>>(curA, rowA, NN);
    scan_k<<<1, 1024>>>(curB, rowB, NN);
    copy_int_k<<<(NN + 255) / 256, 256>>>(rowA, curA, NN);
    copy_int_k<<<(NN + 255) / 256, 256>>>(rowB, curB, NN);
    fill_k<<<(EA + 255) / 256, 256>>>(srcA, dstA, EA, curA, colA);
    fill_k<<<(EB + 255) / 256, 256>>>(srcB, dstB, EB, curB, colB);

    // ---- 3 GAT layers ----
    const float* xin = x;
    float* xout = x0;
    for (int l = 0; l < 3; ++l) {
        feat_k<<<592, 256>>>(xin, lin_w + l * HID * OUTD,
                             att_src + l * OUTD, att_dst + l * OUTD);
        agg_k<<<(NN * 32 + 255) / 256, 256>>>(rowA, colA, bias + l * OUTD, xout, 0);
        agg_k<<<(NN * 32 + 255) / 256, 256>>>(rowB, colB, bias + l * OUTD, xout, OUTD);
        xin = xout;
        xout = (xout == x0) ? x1 : x0;
    }
    const float* xfinal = xin;

    // ---- pooling + final projection ----
    zero_float_k<<<(NG * HID + 255) / 256, 256>>>(pool, NG * HID);
    pool_k<<<(NN * HID + 255) / 256, 256>>>(batch, xfinal);
    final_k<<<(NG * 32 + 127) / 128, 128>>>(fw, fb, out);
}

// round 2
// speedup vs baseline: 1.0792x; 1.0792x over previous
#include <cuda_runtime.h>
#include <cuda_fp16.h>

#define NN 50000
#define NG 500
#define EA 800000
#define EB 3200000
#define ET (EA + EB)
#define HID 128
#define OUTD 64
#define FULLM 0xffffffffu

// ---------------- device scratch (static, no allocation) ----------------
__device__ __half g_h[NN * OUTD];
__device__ float g_ssrc[NN];
__device__ float g_sdst[NN];
__device__ float g_x0[NN * HID];
__device__ float g_x1[NN * HID];
__device__ float g_esc[ET];
__device__ int   g_rowA[NN + 1];
__device__ int   g_colA[EA];
__device__ int   g_curA[NN];
__device__ int   g_rowB[NN + 1];
__device__ int   g_colB[EB];
__device__ int   g_curB[NN];

// ---------------- CSR build ----------------
__global__ void zero2_k() {
    int i = blockIdx.x * blockDim.x + threadIdx.x;
    if (i < NN) g_curA[i] = 0;
    else if (i < 2 * NN) g_curB[i - NN] = 0;
}
__global__ void count_both_k(const int* __restrict__ dA, const int* __restrict__ dB) {
    int i = blockIdx.x * blockDim.x + threadIdx.x;
    if (i < EA) atomicAdd(&g_curA[dA[i]], 1);
    else if (i < ET) atomicAdd(&g_curB[dB[i - EA]], 1);
}
// exclusive scan; block 0 -> set A, block 1 -> set B; also primes cur = row
__global__ void scan_both_k() {
    int* deg = blockIdx.x ? g_curB : g_curA;
    int* row = blockIdx.x ? g_rowB : g_rowA;
    __shared__ int part[1024];
    int t = threadIdx.x;
    const int C = (NN + 1023) / 1024;
    int b = t * C;
    int e = b + C; if (e > NN) e = NN;
    int s = 0;
    for (int i = b; i < e; ++i) s += deg[i];
    part[t] = s;
    __syncthreads();
    for (int off = 1; off < 1024; off <<= 1) {
        int v = (t >= off) ? part[t - off] : 0;
        __syncthreads();
        part[t] += v;
        __syncthreads();
    }
    int run = t ? part[t - 1] : 0;
    for (int i = b; i < e; ++i) {
        int d = deg[i];
        row[i] = run;
        deg[i] = run;   // cur = row start, for fill
        run += d;
    }
    if (t == 1023) row[NN] = part[1023];
}
__global__ void fill_both_k(const int* __restrict__ sA, const int* __restrict__ dA,
                            const int* __restrict__ sB, const int* __restrict__ dB) {
    int i = blockIdx.x * blockDim.x + threadIdx.x;
    if (i < EA) {
        int p = atomicAdd(&g_curA[dA[i]], 1);
        g_colA[p] = sA[i];
    } else if (i < ET) {
        int k = i - EA;
        int p = atomicAdd(&g_curB[dB[k]], 1);
        g_colB[p] = sB[k];
    }
}

// --------- per-layer transform: h = x@W (fp16 out), s_src, s_dst ---------
// lane l owns output channels 2l and 2l+1
__global__ void feat_k(const float* __restrict__ x, const float* __restrict__ W,
                       const float* __restrict__ as_, const float* __restrict__ ad_) {
    __shared__ float Ws[HID * OUTD];
    for (int i = threadIdx.x; i < HID * OUTD; i += blockDim.x) Ws[i] = W[i];
    __syncthreads();
    int lane = threadIdx.x & 31;
    int wid = (blockIdx.x * blockDim.x + threadIdx.x) >> 5;
    int nw = (gridDim.x * blockDim.x) >> 5;
    float2 asv = ((const float2*)as_)[lane];
    float2 adv = ((const float2*)ad_)[lane];
    for (int n = wid; n < NN; n += nw) {
        const float* xr = x + n * HID;
        float xl0 = xr[lane], xl1 = xr[lane + 32], xl2 = xr[lane + 64], xl3 = xr[lane + 96];
        float h0 = 0.f, h1 = 0.f;
#pragma unroll
        for (int k = 0; k < 32; ++k) {
            float xv = __shfl_sync(FULLM, xl0, k);
            float2 wv = ((const float2*)Ws)[k * 32 + lane];
            h0 += xv * wv.x; h1 += xv * wv.y;
        }
#pragma unroll
        for (int k = 0; k < 32; ++k) {
            float xv = __shfl_sync(FULLM, xl1, k);
            float2 wv = ((const float2*)Ws)[(k + 32) * 32 + lane];
            h0 += xv * wv.x; h1 += xv * wv.y;
        }
#pragma unroll
        for (int k = 0; k < 32; ++k) {
            float xv = __shfl_sync(FULLM, xl2, k);
            float2 wv = ((const float2*)Ws)[(k + 64) * 32 + lane];
            h0 += xv * wv.x; h1 += xv * wv.y;
        }
#pragma unroll
        for (int k = 0; k < 32; ++k) {
            float xv = __shfl_sync(FULLM, xl3, k);
            float2 wv = ((const float2*)Ws)[(k + 96) * 32 + lane];
            h0 += xv * wv.x; h1 += xv * wv.y;
        }
        ((__half2*)g_h)[n * 32 + lane] = __floats2half2_rn(h0, h1);
        float s = h0 * asv.x + h1 * asv.y;
        float d = h0 * adv.x + h1 * adv.y;
#pragma unroll
        for (int o = 16; o; o >>= 1) {
            s += __shfl_xor_sync(FULLM, s, o);
            d += __shfl_xor_sync(FULLM, d, o);
        }
        if (lane == 0) { g_ssrc[n] = s; g_sdst[n] = d; }
    }
}

__device__ __forceinline__ float lrelu(float v) { return v > 0.f ? v : 0.2f * v; }

// ------------- GAT aggregation, warp per dst node, both branches ---------
__global__ void agg_k(const float* __restrict__ bias, float* __restrict__ xout) {
    int gw = (blockIdx.x * blockDim.x + threadIdx.x) >> 5;
    int lane = threadIdx.x & 31;
    if (gw >= 2 * NN) return;
    int isB = gw >= NN;
    int n = isB ? gw - NN : gw;
    const int* __restrict__ row = isB ? g_rowB : g_rowA;
    const int* __restrict__ col = isB ? g_colB : g_colA;
    float* __restrict__ esc = isB ? g_esc + EA : g_esc;
    int outOff = isB ? OUTD : 0;

    float sd = g_sdst[n];
    int b = row[n], e = row[n + 1];

    // pass 1: per-edge score -> scratch, running max
    float selfsc = lrelu(g_ssrc[n] + sd);
    float m = selfsc;
    for (int j = b + lane; j < e; j += 32) {
        float ev = lrelu(__ldg(&g_ssrc[col[j]]) + sd);
        esc[j] = ev;
        m = fmaxf(m, ev);
    }
#pragma unroll
    for (int o = 16; o; o >>= 1) m = fmaxf(m, __shfl_xor_sync(FULLM, m, o));

    const __half2* __restrict__ h2 = (const __half2*)g_h;

    // self loop
    float ps = __expf(selfsc - m);
    float2 hv = __half22float2(h2[n * 32 + lane]);
    float a0 = ps * hv.x, a1 = ps * hv.y;
    float z = (lane == 0) ? ps : 0.f;

    // pass 2: full 32-edge chunks, fully unrolled for MLP
    int nfull = b + ((e - b) & ~31);
    for (int j0 = b; j0 < nfull; j0 += 32) {
        int se = col[j0 + lane];
        float pe = __expf(esc[j0 + lane] - m);
        z += pe;
#pragma unroll
        for (int t = 0; t < 32; ++t) {
            float pt = __shfl_sync(FULLM, pe, t);
            int st = __shfl_sync(FULLM, se, t);
            float2 hh = __half22float2(__ldg(&h2[st * 32 + lane]));
            a0 += pt * hh.x; a1 += pt * hh.y;
        }
    }
    // tail
    {
        int j = nfull + lane;
        float pe = 0.f; int se = 0;
        if (j < e) { se = col[j]; pe = __expf(esc[j] - m); }
        z += pe;
        int cnt = e - nfull;
        for (int t = 0; t < cnt; ++t) {
            float pt = __shfl_sync(FULLM, pe, t);
            int st = __shfl_sync(FULLM, se, t);
            float2 hh = __half22float2(__ldg(&h2[st * 32 + lane]));
            a0 += pt * hh.x; a1 += pt * hh.y;
        }
    }
#pragma unroll
    for (int o = 16; o; o >>= 1) z += __shfl_xor_sync(FULLM, z, o);
    float inv = 1.f / z;
    float2 bv = ((const float2*)bias)[lane];
    float2 res;
    res.x = fmaxf(a0 * inv + bv.x, 0.f);
    res.y = fmaxf(a1 * inv + bv.y, 0.f);
    ((float2*)(xout + n * HID + outOff))[lane] = res;
}

// ------------- fused global add pool + final linear ----------------
// batch is sorted: graph g owns a contiguous node range found by binary search
__global__ void pool_final_k(const int* __restrict__ batch, const float* __restrict__ x,
                             const float* __restrict__ fw, const float* __restrict__ fb,
                             float* __restrict__ out) {
    int g = blockIdx.x;
    int t = threadIdx.x;  // 128 threads, one channel each
    __shared__ int bound[2];
    __shared__ float red[4];
    if (t < 2) {
        int target = g + t;
        int lo = 0, hi = NN;
        while (lo < hi) {
            int mid = (lo + hi) >> 1;
            if (batch[mid] < target) lo = mid + 1; else hi = mid;
        }
        bound[t] = lo;
    }
    __syncthreads();
    int lo = bound[0], hi = bound[1];
    float acc = 0.f;
    for (int n = lo; n < hi; ++n) acc += x[n * HID + t];
    acc *= fw[t];
#pragma unroll
    for (int o = 16; o; o >>= 1) acc += __shfl_xor_sync(FULLM, acc, o);
    if ((t & 31) == 0) red[t >> 5] = acc;
    __syncthreads();
    if (t == 0) out[g] = red[0] + red[1] + red[2] + red[3] + fb[0];
}

// ---------------- host launcher ----------------
extern "C" void kernel_launch(void* const* d_in, const int* in_sizes, int n_in,
                              void* d_out, int out_size) {
    const float* x       = (const float*)d_in[0];
    const int*   ei      = (const int*)d_in[1];
    const int*   di      = (const int*)d_in[2];
    const int*   batch   = (const int*)d_in[3];
    const float* lin_w   = (const float*)d_in[4];
    const float* att_src = (const float*)d_in[5];
    const float* att_dst = (const float*)d_in[6];
    const float* bias    = (const float*)d_in[7];
    const float* fw      = (const float*)d_in[8];
    const float* fb      = (const float*)d_in[9];
    float* out = (float*)d_out;

    void* p;
    cudaGetSymbolAddress(&p, g_x0); float* x0 = (float*)p;
    cudaGetSymbolAddress(&p, g_x1); float* x1 = (float*)p;

    const int* srcA = ei;  const int* dstA = ei + EA;
    const int* srcB = di;  const int* dstB = di + EB;

    // ---- build CSR (by dst) for both edge sets ----
    zero2_k<<<(2 * NN + 255) / 256, 256>>>();
    count_both_k<<<(ET + 255) / 256, 256>>>(dstA, dstB);
    scan_both_k<<<2, 1024>>>();
    fill_both_k<<<(ET + 255) / 256, 256>>>(srcA, dstA, srcB, dstB);

    // ---- 3 GAT layers ----
    const float* xin = x;
    float* xo = x0;
    for (int l = 0; l < 3; ++l) {
        feat_k<<<592, 256>>>(xin, lin_w + l * HID * OUTD,
                             att_src + l * OUTD, att_dst + l * OUTD);
        agg_k<<<(2 * NN * 32 + 255) / 256, 256>>>(bias + l * OUTD, xo);
        xin = xo;
        xo = (xo == x0) ? x1 : x0;
    }

    // ---- fused pooling + final projection ----
    pool_final_k<<<NG, 128>>>(batch, xin, fw, fb, out);
}